// round 10
// baseline (speedup 1.0000x reference)
#include <cuda_runtime.h>
#include <cuda_bf16.h>
#include <cstdint>

#define BATCH 64
#define SEQ   512
#define DIM   1024
#define TAGS  32
#define NSUB  32     // 16-step sub-chunks per batch

#define AF_STRIDE 68
#define WF_STRIDE 36
#define AF_WORDS (64 * AF_STRIDE)   // 4352 floats per buffer
#define WF_WORDS (64 * WF_STRIDE)   // 2304 floats per buffer
#define SMEM_DYN_BYTES ((2 * AF_WORDS + 2 * WF_WORDS + 64 * 32) * 4)  // 61440

// Per-(batch,subchunk) chain outputs + combine state.
__device__ float g_fvec[BATCH][NSUB][TAGS];
__device__ float g_bvec[BATCH][NSUB][TAGS];
__device__ float g_flog[BATCH][NSUB];
__device__ float g_blog[BATCH][NSUB];
__device__ float g_scorep[BATCH][8];
__device__ float g_llh[BATCH];
__device__ int   g_len[BATCH];
__device__ int   g_doneb[BATCH];
__device__ int   g_done;

// ---------------------------------------------------------------------------
__device__ __forceinline__ void mma_tf32(float& d0, float& d1, float& d2, float& d3,
                                         uint32_t a0, uint32_t a1, uint32_t a2, uint32_t a3,
                                         uint32_t b0, uint32_t b1) {
    asm volatile(
        "mma.sync.aligned.m16n8k8.row.col.f32.tf32.tf32.f32 "
        "{%0,%1,%2,%3}, {%4,%5,%6,%7}, {%8,%9}, {%0,%1,%2,%3};\n"
        : "+f"(d0), "+f"(d1), "+f"(d2), "+f"(d3)
        : "r"(a0), "r"(a1), "r"(a2), "r"(a3), "r"(b0), "r"(b1));
}

__device__ __forceinline__ void cp16(uint32_t dst, const void* src) {
    asm volatile("cp.async.cg.shared.global [%0], [%1], 16;" :: "r"(dst), "l"(src));
}

__device__ __forceinline__ uint32_t f2u(float f) { return __float_as_uint(f); }

__device__ __forceinline__ int tag_at(const int* __restrict__ tg, int idx, bool is64) {
    return is64 ? __ldg(tg + 2 * idx) : __ldg(tg + idx);
}

// 32-FMA dot of replicated vector (smem) with per-lane coefficients.
__device__ __forceinline__ float dot32(const float* __restrict__ q,
                                       const float* __restrict__ Tc) {
    const float4 q0 = *reinterpret_cast<const float4*>(q + 0);
    const float4 q1 = *reinterpret_cast<const float4*>(q + 4);
    const float4 q2 = *reinterpret_cast<const float4*>(q + 8);
    const float4 q3 = *reinterpret_cast<const float4*>(q + 12);
    const float4 q4 = *reinterpret_cast<const float4*>(q + 16);
    const float4 q5 = *reinterpret_cast<const float4*>(q + 20);
    const float4 q6 = *reinterpret_cast<const float4*>(q + 24);
    const float4 q7 = *reinterpret_cast<const float4*>(q + 28);
    float s0 = q0.x * Tc[0],  s1 = q0.y * Tc[1];
    float s2 = q0.z * Tc[2],  s3 = q0.w * Tc[3];
    s0 = fmaf(q1.x, Tc[4],  s0); s1 = fmaf(q1.y, Tc[5],  s1);
    s2 = fmaf(q1.z, Tc[6],  s2); s3 = fmaf(q1.w, Tc[7],  s3);
    s0 = fmaf(q2.x, Tc[8],  s0); s1 = fmaf(q2.y, Tc[9],  s1);
    s2 = fmaf(q2.z, Tc[10], s2); s3 = fmaf(q2.w, Tc[11], s3);
    s0 = fmaf(q3.x, Tc[12], s0); s1 = fmaf(q3.y, Tc[13], s1);
    s2 = fmaf(q3.z, Tc[14], s2); s3 = fmaf(q3.w, Tc[15], s3);
    s0 = fmaf(q4.x, Tc[16], s0); s1 = fmaf(q4.y, Tc[17], s1);
    s2 = fmaf(q4.z, Tc[18], s2); s3 = fmaf(q4.w, Tc[19], s3);
    s0 = fmaf(q5.x, Tc[20], s0); s1 = fmaf(q5.y, Tc[21], s1);
    s2 = fmaf(q5.z, Tc[22], s2); s3 = fmaf(q5.w, Tc[23], s3);
    s0 = fmaf(q6.x, Tc[24], s0); s1 = fmaf(q6.y, Tc[25], s1);
    s2 = fmaf(q6.z, Tc[26], s2); s3 = fmaf(q6.w, Tc[27], s3);
    s0 = fmaf(q7.x, Tc[28], s0); s1 = fmaf(q7.y, Tc[29], s1);
    s2 = fmaf(q7.z, Tc[30], s2); s3 = fmaf(q7.w, Tc[31], s3);
    return (s0 + s1) + (s2 + s3);
}

__device__ __forceinline__ int warp_len(const int* tags, int base, bool is64, int lane) {
    const unsigned F = 0xffffffffu;
    int len = 0;
#pragma unroll
    for (int k = 0; k < 16; k++) {
        const int tv = tag_at(tags, base + k * 32 + lane, is64);
        len += __popc(__ballot_sync(F, tv != -1));
    }
    return len;
}

// ---------------------------------------------------------------------------
// 512 blocks. Block = (batch b, 64-row chunk c). cp.async GEMM -> smem xs,
// then warps 0-3: fwd chains of 4 16-step sub-chunks; warps 4-7: bwd chains.
// ---------------------------------------------------------------------------
__global__ __launch_bounds__(256, 3)
void fused_kernel(const float* __restrict__ feat,
                  const int*   __restrict__ tags,
                  const float* __restrict__ Wg,
                  const float* __restrict__ bias,
                  const float* __restrict__ start_t,
                  const float* __restrict__ end_t,
                  const float* __restrict__ trans,
                  float* __restrict__ out) {
    extern __shared__ float sdyn[];
    float* Af = sdyn;                             // [2][64*AF_STRIDE]
    float* Wf = sdyn + 2 * AF_WORDS;              // [2][64*WF_STRIDE]
    float* xs = sdyn + 2 * AF_WORDS + 2 * WF_WORDS;  // [64*32]

    __shared__ __align__(16) float psF[4][2][32];
    __shared__ __align__(16) float psB[4][2][32];
    __shared__ int s_win, s_win2;

    const unsigned F = 0xffffffffu;
    const int tid  = threadIdx.x;
    const int lane = tid & 31;
    const int w    = tid >> 5;
    const int m0   = blockIdx.x * 64;
    const int b    = blockIdx.x >> 3;     // batch
    const int c    = blockIdx.x & 7;      // 64-row chunk

    // ======================= GEMM: x-chunk -> xs ==========================
    {
        const int rb = (w & 3) * 16;
        const int nb = (w >> 2) * 16;
        const int g  = lane >> 2;
        const int t  = lane & 3;

        float acc[2][4];
#pragma unroll
        for (int f = 0; f < 2; f++)
#pragma unroll
            for (int j = 0; j < 4; j++) acc[f][j] = 0.f;

        // indices for cp.async staging
        const int arow = tid >> 4, aseg = tid & 15;       // + j*16 rows
        const int wrow = tid >> 3, wseg = tid & 7;        // + j*32 rows

#define ISSUE_CHUNK(CC, Q)                                                     \
    {                                                                          \
        const int kc_ = (CC) * 64;                                             \
        uint32_t ab_ = (uint32_t)__cvta_generic_to_shared(Af + (Q) * AF_WORDS);\
        uint32_t wb_ = (uint32_t)__cvta_generic_to_shared(Wf + (Q) * WF_WORDS);\
        _Pragma("unroll")                                                      \
        for (int j = 0; j < 4; j++) {                                          \
            const int row = arow + j * 16;                                     \
            cp16(ab_ + (row * AF_STRIDE + aseg * 4) * 4,                       \
                 feat + (size_t)(m0 + row) * DIM + kc_ + aseg * 4);            \
        }                                                                      \
        _Pragma("unroll")                                                      \
        for (int j = 0; j < 2; j++) {                                          \
            const int row = wrow + j * 32;                                     \
            cp16(wb_ + (row * WF_STRIDE + wseg * 4) * 4,                       \
                 Wg + (size_t)(kc_ + row) * TAGS + wseg * 4);                  \
        }                                                                      \
        asm volatile("cp.async.commit_group;");                                \
    }

        ISSUE_CHUNK(0, 0)

        for (int cc = 0; cc < 16; cc++) {
            const int q = cc & 1;
            if (cc < 15) {
                ISSUE_CHUNK(cc + 1, q ^ 1)
                asm volatile("cp.async.wait_group 1;");
            } else {
                asm volatile("cp.async.wait_group 0;");
            }
            __syncthreads();

            const float* A  = Af + q * AF_WORDS;
            const float* Bt = Wf + q * WF_WORDS;
#pragma unroll
            for (int ks = 0; ks < 8; ks++) {
                const int kb = ks * 8;
                const uint32_t a0 = f2u(A[(rb + g)     * AF_STRIDE + kb + t]);
                const uint32_t a1 = f2u(A[(rb + g + 8) * AF_STRIDE + kb + t]);
                const uint32_t a2 = f2u(A[(rb + g)     * AF_STRIDE + kb + 4 + t]);
                const uint32_t a3 = f2u(A[(rb + g + 8) * AF_STRIDE + kb + 4 + t]);
#pragma unroll
                for (int f = 0; f < 2; f++) {
                    const uint32_t b0 = f2u(Bt[(kb + t)     * WF_STRIDE + nb + 8 * f + g]);
                    const uint32_t b1 = f2u(Bt[(kb + 4 + t) * WF_STRIDE + nb + 8 * f + g]);
                    mma_tf32(acc[f][0], acc[f][1], acc[f][2], acc[f][3],
                             a0, a1, a2, a3, b0, b1);
                }
            }
            __syncthreads();
        }
#undef ISSUE_CHUNK

        // epilogue -> xs
        const int c2 = 2 * t;
        const int lrow = rb + g;
#pragma unroll
        for (int f = 0; f < 2; f++) {
            const int col = nb + 8 * f + c2;
            const float bv0 = bias[col], bv1 = bias[col + 1];
            *reinterpret_cast<float2*>(xs + lrow * 32 + col) =
                make_float2(acc[f][0] + bv0, acc[f][1] + bv1);
            *reinterpret_cast<float2*>(xs + (lrow + 8) * 32 + col) =
                make_float2(acc[f][2] + bv0, acc[f][3] + bv1);
        }
    }
    __syncthreads();   // xs ready

    // ======================= chains + numerator ===========================
    const int v1 = tags[2 * lane + 1];
    const int v2 = tags[2 * lane + 65];
    const bool okd = (v1 == 0 || v1 == -1) && (v2 == 0 || v2 == -1);
    const bool is64 = __all_sync(F, okd);
    const int base = b * SEQ;

    const int len = warp_len(tags, base, is64, lane);
    const int cl = (len - 1) >> 4;            // last active sub-chunk

    if (w < 4) {
        // ----- forward chain for sub-chunk cc = 4c + w -----
        const int cc = 4 * c + w;
        if (cc <= cl - 1) {
            float Tc[32];
#pragma unroll
            for (int i = 0; i < 32; i++)
                Tc[i] = __expf(__ldg(trans + i * 32 + lane));

            const int lo = 16 * w;            // local row base
            float p, Cf = 0.f;
            int tloc, nst;
            if (cc == 0) { p = __expf(__ldg(start_t + lane) + xs[lane]); tloc = 1;  nst = 15; }
            else         { p = 1.f;                                      tloc = lo; nst = 16; }
            psF[w][0][lane] = p;
            int bp = 0;

#define FSTEP(RENORM)                                                          \
    {                                                                          \
        __syncwarp();                                                          \
        const float m_ = psF[w][bp][0];                                        \
        const float s_ = dot32(&psF[w][bp][0], Tc);                            \
        float pn = s_ * __expf(xs[tloc * 32 + lane]);                          \
        if (RENORM) {                                                          \
            float inv_;                                                        \
            asm("rcp.approx.f32 %0, %1;" : "=f"(inv_) : "f"(m_));              \
            pn *= inv_; Cf += __logf(m_);                                      \
        }                                                                      \
        p = pn; psF[w][bp ^ 1][lane] = p; bp ^= 1; tloc++;                     \
    }
            const int n4 = nst >> 2;
            for (int k = 0; k < n4; k++) { FSTEP(0) FSTEP(0) FSTEP(0) FSTEP(1) }
            const int rem = nst & 3;
            for (int k = 0; k < rem; k++) { FSTEP(0) }
#undef FSTEP
            const float m = __shfl_sync(F, p, 0);
            float inv; asm("rcp.approx.f32 %0, %1;" : "=f"(inv) : "f"(m));
            p *= inv; Cf += __logf(m);
            g_fvec[b][cc][lane] = p;
            if (lane == 0) g_flog[b][cc] = Cf;
        }
        // ----- numerator partial (warp 0 only), rows [64c, 64c+63] -----
        if (w == 0) {
            if (lane == 0) g_len[b] = len;
            float acc = 0.f;
#pragma unroll
            for (int r = 0; r < 2; r++) {
                const int t = 64 * c + r * 32 + lane;
                const int tg = tag_at(tags, base + t, is64);
                const bool valid = tg >= 0;
                int tgp = __shfl_up_sync(F, tg, 1);
                if (lane == 0) tgp = (t == 0) ? 0 : tag_at(tags, base + t - 1, is64);
                const int tgc = valid ? tg : 0;
                const int tgpc = tgp >= 0 ? tgp : 0;
                const float em = xs[(r * 32 + lane) * 32 + tgc];
                const float tr = (t == 0) ? __ldg(start_t + tgc)
                                          : __ldg(trans + tgpc * 32 + tgc);
                float co = valid ? (tr + em) : 0.f;
                if (valid && t == len - 1) co += __ldg(end_t + tgc);
                acc += co;
            }
#pragma unroll
            for (int off = 16; off > 0; off >>= 1)
                acc += __shfl_xor_sync(F, acc, off);
            if (lane == 0) g_scorep[b][c] = acc;
        }
    } else {
        // ----- backward chain for sub-chunk cc = 4c + (w-4) -----
        const int lw = w - 4;
        const int cc = 4 * c + lw;
        if (cc >= 1 && cc <= cl) {
            float Tr[32];
#pragma unroll
            for (int j = 0; j < 32; j++)
                Tr[j] = __expf(__ldg(trans + lane * 32 + j));

            const int lo = 16 * lw;                             // local
            const int hi_g = (16 * cc + 15 < len - 1) ? 16 * cc + 15 : len - 1;
            const int hi = hi_g - 64 * c;                       // local
            const int nst = hi - lo + 1;
            float wv = (cc == cl) ? __expf(__ldg(end_t + lane)) : 1.f;
            float Gb = 0.f;
            int tloc = hi;
            psB[lw][0][lane] = wv * __expf(xs[tloc * 32 + lane]);
            int bp = 0;

#define BSTEP(RENORM)                                                          \
    {                                                                          \
        __syncwarp();                                                          \
        const float m_ = psB[lw][bp][0];                                       \
        float s_ = dot32(&psB[lw][bp][0], Tr);                                 \
        if (RENORM) {                                                          \
            float inv_;                                                        \
            asm("rcp.approx.f32 %0, %1;" : "=f"(inv_) : "f"(m_));              \
            s_ *= inv_; Gb += __logf(m_);                                      \
        }                                                                      \
        wv = s_;                                                               \
        tloc--;                                                                \
        const int il_ = tloc < lo ? lo : tloc;                                 \
        psB[lw][bp ^ 1][lane] = wv * __expf(xs[il_ * 32 + lane]);              \
        bp ^= 1;                                                               \
    }
            const int n4 = nst >> 2;
            for (int k = 0; k < n4; k++) { BSTEP(0) BSTEP(0) BSTEP(0) BSTEP(1) }
            const int rem = nst & 3;
            for (int k = 0; k < rem; k++) { BSTEP(0) }
#undef BSTEP
            const float m = __shfl_sync(F, wv, 0);
            float inv; asm("rcp.approx.f32 %0, %1;" : "=f"(inv) : "f"(m));
            wv *= inv; Gb += __logf(m);
            g_bvec[b][cc][lane] = wv;
            if (lane == 0) g_blog[b][cc] = Gb;
        }
    }

    // ======================= tickets + combine ============================
    __syncthreads();
    if (tid == 0) {
        __threadfence();
        const int old = atomicAdd(&g_doneb[b], 1);
        s_win = (old == 7);
        s_win2 = 0;
    }
    __syncthreads();
    if (!s_win) return;

    if (w == 0) {
        // per-batch combine (warp 0): junction terms independent per lane.
        __threadfence();
        const int lenb = g_len[b];
        const int clb = (lenb - 1) >> 4;
        float term = 0.f;
        if (lane >= 1 && lane <= clb) {
            float dotv = 0.f;
            const float* bv = g_bvec[b][lane];
            const float* fv = g_fvec[b][lane - 1];
#pragma unroll
            for (int i = 0; i < 32; i++) dotv += bv[i] * fv[i];
            term = g_blog[b][lane] + __logf(dotv);
            if (lane <= clb - 1) {
                float sumv = 0.f;
                const float* fc = g_fvec[b][lane];
#pragma unroll
                for (int i = 0; i < 32; i++) sumv += fc[i];
                term -= __logf(sumv);
            }
        }
#pragma unroll
        for (int off = 16; off > 0; off >>= 1)
            term += __shfl_xor_sync(F, term, off);
        const float logZ = g_flog[b][0] + term;

        if (lane == 0) {
            float score = 0.f;
#pragma unroll
            for (int cc2 = 0; cc2 < 8; cc2++) score += g_scorep[b][cc2];
            g_llh[b] = score - logZ;
        }
    }
    __syncthreads();
    if (tid == 0) {
        __threadfence();
        const int o2 = atomicAdd(&g_done, 1);
        s_win2 = (o2 == BATCH - 1);
    }
    __syncthreads();
    if (s_win2 && w == 0) {
        __threadfence();
        float v = g_llh[lane] + g_llh[lane + 32];
#pragma unroll
        for (int off = 16; off > 0; off >>= 1)
            v += __shfl_xor_sync(F, v, off);
        if (lane == 0) out[0] = -v * (1.0f / (float)BATCH);
        g_doneb[lane] = 0;
        g_doneb[lane + 32] = 0;
        if (lane == 0) g_done = 0;
    }
}

// ---------------------------------------------------------------------------
extern "C" void kernel_launch(void* const* d_in, const int* in_sizes, int n_in,
                              void* d_out, int out_size) {
    const float* feat    = (const float*)d_in[0];
    const int*   tags    = (const int*)  d_in[1];
    const float* W       = (const float*)d_in[2];
    const float* bias    = (const float*)d_in[3];
    const float* start_t = (const float*)d_in[4];
    const float* end_t   = (const float*)d_in[5];
    const float* trans   = (const float*)d_in[6];
    float* out = (float*)d_out;

    cudaFuncSetAttribute(fused_kernel,
                         cudaFuncAttributeMaxDynamicSharedMemorySize,
                         SMEM_DYN_BYTES);
    fused_kernel<<<BATCH * 8, 256, SMEM_DYN_BYTES>>>(
        feat, tags, W, bias, start_t, end_t, trans, out);
}

// round 11
// speedup vs baseline: 1.3571x; 1.3571x over previous
#include <cuda_runtime.h>
#include <cuda_bf16.h>
#include <cstdint>

#define BATCH 64
#define SEQ   512
#define DIM   1024
#define TAGS  32
#define NSUB  32     // 16-step sub-chunks per batch

// Per-(batch,subchunk) chain outputs + combine state.
__device__ float g_fvec[BATCH][NSUB][TAGS];
__device__ float g_bvec[BATCH][NSUB][TAGS];
__device__ float g_flog[BATCH][NSUB];
__device__ float g_blog[BATCH][NSUB];
__device__ float g_scorep[BATCH][4];
__device__ float g_llh[BATCH];
__device__ int   g_len[BATCH];
__device__ int   g_doneb[BATCH];
__device__ int   g_done;

// ---------------------------------------------------------------------------
__device__ __forceinline__ void mma_bf16(float& d0, float& d1, float& d2, float& d3,
                                         uint32_t a0, uint32_t a1, uint32_t a2, uint32_t a3,
                                         uint32_t b0, uint32_t b1) {
    asm volatile(
        "mma.sync.aligned.m16n8k16.row.col.f32.bf16.bf16.f32 "
        "{%0,%1,%2,%3}, {%4,%5,%6,%7}, {%8,%9}, {%0,%1,%2,%3};\n"
        : "+f"(d0), "+f"(d1), "+f"(d2), "+f"(d3)
        : "r"(a0), "r"(a1), "r"(a2), "r"(a3), "r"(b0), "r"(b1));
}

__device__ __forceinline__ uint32_t pack_bf16(float lo, float hi) {
    __nv_bfloat162 h = __floats2bfloat162_rn(lo, hi);
    return *reinterpret_cast<uint32_t*>(&h);
}

__device__ __forceinline__ int tag_at(const int* __restrict__ tg, int idx, bool is64) {
    return is64 ? __ldg(tg + 2 * idx) : __ldg(tg + idx);
}

// 32-FMA dot of replicated vector (smem) with per-lane coefficients.
__device__ __forceinline__ float dot32(const float* __restrict__ q,
                                       const float* __restrict__ Tc) {
    const float4 q0 = *reinterpret_cast<const float4*>(q + 0);
    const float4 q1 = *reinterpret_cast<const float4*>(q + 4);
    const float4 q2 = *reinterpret_cast<const float4*>(q + 8);
    const float4 q3 = *reinterpret_cast<const float4*>(q + 12);
    const float4 q4 = *reinterpret_cast<const float4*>(q + 16);
    const float4 q5 = *reinterpret_cast<const float4*>(q + 20);
    const float4 q6 = *reinterpret_cast<const float4*>(q + 24);
    const float4 q7 = *reinterpret_cast<const float4*>(q + 28);
    float s0 = q0.x * Tc[0],  s1 = q0.y * Tc[1];
    float s2 = q0.z * Tc[2],  s3 = q0.w * Tc[3];
    s0 = fmaf(q1.x, Tc[4],  s0); s1 = fmaf(q1.y, Tc[5],  s1);
    s2 = fmaf(q1.z, Tc[6],  s2); s3 = fmaf(q1.w, Tc[7],  s3);
    s0 = fmaf(q2.x, Tc[8],  s0); s1 = fmaf(q2.y, Tc[9],  s1);
    s2 = fmaf(q2.z, Tc[10], s2); s3 = fmaf(q2.w, Tc[11], s3);
    s0 = fmaf(q3.x, Tc[12], s0); s1 = fmaf(q3.y, Tc[13], s1);
    s2 = fmaf(q3.z, Tc[14], s2); s3 = fmaf(q3.w, Tc[15], s3);
    s0 = fmaf(q4.x, Tc[16], s0); s1 = fmaf(q4.y, Tc[17], s1);
    s2 = fmaf(q4.z, Tc[18], s2); s3 = fmaf(q4.w, Tc[19], s3);
    s0 = fmaf(q5.x, Tc[20], s0); s1 = fmaf(q5.y, Tc[21], s1);
    s2 = fmaf(q5.z, Tc[22], s2); s3 = fmaf(q5.w, Tc[23], s3);
    s0 = fmaf(q6.x, Tc[24], s0); s1 = fmaf(q6.y, Tc[25], s1);
    s2 = fmaf(q6.z, Tc[26], s2); s3 = fmaf(q6.w, Tc[27], s3);
    s0 = fmaf(q7.x, Tc[28], s0); s1 = fmaf(q7.y, Tc[29], s1);
    s2 = fmaf(q7.z, Tc[30], s2); s3 = fmaf(q7.w, Tc[31], s3);
    return (s0 + s1) + (s2 + s3);
}

__device__ __forceinline__ int warp_len(const int* tags, int base, bool is64, int lane) {
    const unsigned F = 0xffffffffu;
    int len = 0;
#pragma unroll
    for (int k = 0; k < 16; k++) {
        const int tv = tag_at(tags, base + k * 32 + lane, is64);
        len += __popc(__ballot_sync(F, tv != -1));
    }
    return len;
}

#define ASTRIDE 36   // 36 mod 32 = 4 -> A-fragment reads conflict-free
#define WSTRIDE 40   // (kw+t)*40 + nb*8f+g conflict-free

// ---------------------------------------------------------------------------
// 256 blocks = single wave. Block = (batch b, 128-row chunk c in 0..3).
// GEMM (M=128, K-chunk 64, bf16 mma, register-staged) -> smem xs; then each
// warp w runs the fwd chain and bwd chain of sub-chunk cc = 8c + w (16 steps
// each); warp 0 adds the numerator partial. Tickets combine per batch.
// ---------------------------------------------------------------------------
__global__ __launch_bounds__(256, 2)
void fused_kernel(const float* __restrict__ feat,
                  const int*   __restrict__ tags,
                  const float* __restrict__ Wg,
                  const float* __restrict__ bias,
                  const float* __restrict__ start_t,
                  const float* __restrict__ end_t,
                  const float* __restrict__ trans,
                  float* __restrict__ out) {
    __shared__ uint32_t Asm[128 * ASTRIDE];          // 18.4 KB
    __shared__ uint32_t Wp [32 * WSTRIDE];           //  5.1 KB
    __shared__ __align__(16) float xs[128 * 32];     // 16.4 KB
    __shared__ __align__(16) float psF[8][2][32];    //  2.0 KB
    __shared__ __align__(16) float psB[8][2][32];    //  2.0 KB
    __shared__ int s_win, s_win2;

    const unsigned F = 0xffffffffu;
    const int tid  = threadIdx.x;
    const int lane = tid & 31;
    const int w    = tid >> 5;
    const int m0   = blockIdx.x * 128;
    const int b    = blockIdx.x >> 2;     // batch
    const int c    = blockIdx.x & 3;      // 128-row chunk

    // ======================= GEMM: x-chunk -> xs ==========================
    {
        float4 areg[8];            // 128 rows x 16 float4 / 256 thr
        float2 wreg[4];            // 32 kp x 32 n / 256 thr

        // preload chunk 0
#pragma unroll
        for (int i = 0; i < 8; i++) {
            const int idx = tid + i * 256;
            const int row = idx >> 4, kq = idx & 15;
            areg[i] = *reinterpret_cast<const float4*>(
                feat + (size_t)(m0 + row) * DIM + 4 * kq);
        }
#pragma unroll
        for (int i = 0; i < 4; i++) {
            const int idx = tid + i * 256;
            const int kp = idx >> 5, n = idx & 31;
            wreg[i].x = Wg[(size_t)(2 * kp) * TAGS + n];
            wreg[i].y = Wg[(size_t)(2 * kp + 1) * TAGS + n];
        }

        float acc[4][4];
#pragma unroll
        for (int f = 0; f < 4; f++)
#pragma unroll
            for (int j = 0; j < 4; j++) acc[f][j] = 0.f;

        const int rb = w * 16;
        const int g  = lane >> 2;
        const int t  = lane & 3;

        for (int cc = 0; cc < 16; cc++) {
#pragma unroll
            for (int i = 0; i < 8; i++) {
                const int idx = tid + i * 256;
                const int row = idx >> 4, kq = idx & 15;
                Asm[row * ASTRIDE + 2 * kq]     = pack_bf16(areg[i].x, areg[i].y);
                Asm[row * ASTRIDE + 2 * kq + 1] = pack_bf16(areg[i].z, areg[i].w);
            }
#pragma unroll
            for (int i = 0; i < 4; i++) {
                const int idx = tid + i * 256;
                const int kp = idx >> 5, n = idx & 31;
                Wp[kp * WSTRIDE + n] = pack_bf16(wreg[i].x, wreg[i].y);
            }
            __syncthreads();

            if (cc < 15) {
                const int kc = (cc + 1) * 64;
#pragma unroll
                for (int i = 0; i < 8; i++) {
                    const int idx = tid + i * 256;
                    const int row = idx >> 4, kq = idx & 15;
                    areg[i] = *reinterpret_cast<const float4*>(
                        feat + (size_t)(m0 + row) * DIM + kc + 4 * kq);
                }
#pragma unroll
                for (int i = 0; i < 4; i++) {
                    const int idx = tid + i * 256;
                    const int kp = idx >> 5, n = idx & 31;
                    wreg[i].x = Wg[(size_t)(kc + 2 * kp) * TAGS + n];
                    wreg[i].y = Wg[(size_t)(kc + 2 * kp + 1) * TAGS + n];
                }
            }

#pragma unroll
            for (int kf = 0; kf < 4; kf++) {
                const int kw = 8 * kf;
                const uint32_t a0 = Asm[(rb + g)     * ASTRIDE + kw + t];
                const uint32_t a1 = Asm[(rb + g + 8) * ASTRIDE + kw + t];
                const uint32_t a2 = Asm[(rb + g)     * ASTRIDE + kw + 4 + t];
                const uint32_t a3 = Asm[(rb + g + 8) * ASTRIDE + kw + 4 + t];
#pragma unroll
                for (int f = 0; f < 4; f++) {
                    const uint32_t b0 = Wp[(kw + t)     * WSTRIDE + 8 * f + g];
                    const uint32_t b1 = Wp[(kw + 4 + t) * WSTRIDE + 8 * f + g];
                    mma_bf16(acc[f][0], acc[f][1], acc[f][2], acc[f][3],
                             a0, a1, a2, a3, b0, b1);
                }
            }
            __syncthreads();
        }

        // epilogue -> xs
        const int c2 = 2 * t;
        const int lrow = rb + g;
#pragma unroll
        for (int f = 0; f < 4; f++) {
            const int col = 8 * f + c2;
            const float bv0 = bias[col], bv1 = bias[col + 1];
            *reinterpret_cast<float2*>(xs + lrow * 32 + col) =
                make_float2(acc[f][0] + bv0, acc[f][1] + bv1);
            *reinterpret_cast<float2*>(xs + (lrow + 8) * 32 + col) =
                make_float2(acc[f][2] + bv0, acc[f][3] + bv1);
        }
    }
    __syncthreads();   // xs ready

    // ======================= chains + numerator ===========================
    const int v1 = tags[2 * lane + 1];
    const int v2 = tags[2 * lane + 65];
    const bool okd = (v1 == 0 || v1 == -1) && (v2 == 0 || v2 == -1);
    const bool is64 = __all_sync(F, okd);
    const int base = b * SEQ;

    const int len = warp_len(tags, base, is64, lane);
    const int cl = (len - 1) >> 4;            // last active sub-chunk
    const int cc = 8 * c + w;                 // this warp's sub-chunk
    const int lo = 16 * w;                    // local row base

    // ----- forward chain for sub-chunk cc -----
    if (cc <= cl - 1) {
        float Tc[32];
#pragma unroll
        for (int i = 0; i < 32; i++)
            Tc[i] = __expf(__ldg(trans + i * 32 + lane));

        float p, Cf = 0.f;
        int tloc, nst;
        if (cc == 0) { p = __expf(__ldg(start_t + lane) + xs[lane]); tloc = 1;  nst = 15; }
        else         { p = 1.f;                                      tloc = lo; nst = 16; }
        psF[w][0][lane] = p;
        int bp = 0;

#define FSTEP(RENORM)                                                          \
    {                                                                          \
        __syncwarp();                                                          \
        const float m_ = psF[w][bp][0];                                        \
        const float s_ = dot32(&psF[w][bp][0], Tc);                            \
        float pn = s_ * __expf(xs[tloc * 32 + lane]);                          \
        if (RENORM) {                                                          \
            float inv_;                                                        \
            asm("rcp.approx.f32 %0, %1;" : "=f"(inv_) : "f"(m_));              \
            pn *= inv_; Cf += __logf(m_);                                      \
        }                                                                      \
        p = pn; psF[w][bp ^ 1][lane] = p; bp ^= 1; tloc++;                     \
    }
        const int n4 = nst >> 2;
        for (int k = 0; k < n4; k++) { FSTEP(0) FSTEP(0) FSTEP(0) FSTEP(1) }
        const int rem = nst & 3;
        for (int k = 0; k < rem; k++) { FSTEP(0) }
#undef FSTEP
        const float m = __shfl_sync(F, p, 0);
        float inv; asm("rcp.approx.f32 %0, %1;" : "=f"(inv) : "f"(m));
        p *= inv; Cf += __logf(m);
        g_fvec[b][cc][lane] = p;
        if (lane == 0) g_flog[b][cc] = Cf;
    }

    // ----- backward chain for sub-chunk cc -----
    if (cc >= 1 && cc <= cl) {
        float Tr[32];
#pragma unroll
        for (int j = 0; j < 32; j++)
            Tr[j] = __expf(__ldg(trans + lane * 32 + j));

        const int hi_g = (16 * cc + 15 < len - 1) ? 16 * cc + 15 : len - 1;
        const int hi = hi_g - 128 * c;                      // local
        const int nst = hi - lo + 1;
        float wv = (cc == cl) ? __expf(__ldg(end_t + lane)) : 1.f;
        float Gb = 0.f;
        int tloc = hi;
        psB[w][0][lane] = wv * __expf(xs[tloc * 32 + lane]);
        int bp = 0;

#define BSTEP(RENORM)                                                          \
    {                                                                          \
        __syncwarp();                                                          \
        const float m_ = psB[w][bp][0];                                        \
        float s_ = dot32(&psB[w][bp][0], Tr);                                  \
        if (RENORM) {                                                          \
            float inv_;                                                        \
            asm("rcp.approx.f32 %0, %1;" : "=f"(inv_) : "f"(m_));              \
            s_ *= inv_; Gb += __logf(m_);                                      \
        }                                                                      \
        wv = s_;                                                               \
        tloc--;                                                                \
        const int il_ = tloc < lo ? lo : tloc;                                 \
        psB[w][bp ^ 1][lane] = wv * __expf(xs[il_ * 32 + lane]);               \
        bp ^= 1;                                                               \
    }
        const int n4 = nst >> 2;
        for (int k = 0; k < n4; k++) { BSTEP(0) BSTEP(0) BSTEP(0) BSTEP(1) }
        const int rem = nst & 3;
        for (int k = 0; k < rem; k++) { BSTEP(0) }
#undef BSTEP
        const float m = __shfl_sync(F, wv, 0);
        float inv; asm("rcp.approx.f32 %0, %1;" : "=f"(inv) : "f"(m));
        wv *= inv; Gb += __logf(m);
        g_bvec[b][cc][lane] = wv;
        if (lane == 0) g_blog[b][cc] = Gb;
    }

    // ----- numerator partial (warp 0), rows [128c, 128c+127] -----
    if (w == 0) {
        if (lane == 0) g_len[b] = len;
        float acc = 0.f;
#pragma unroll
        for (int r = 0; r < 4; r++) {
            const int t = 128 * c + r * 32 + lane;
            const int tg = tag_at(tags, base + t, is64);
            const bool valid = tg >= 0;
            int tgp = __shfl_up_sync(F, tg, 1);
            if (lane == 0) tgp = (t == 0) ? 0 : tag_at(tags, base + t - 1, is64);
            const int tgc = valid ? tg : 0;
            const int tgpc = tgp >= 0 ? tgp : 0;
            const float em = xs[(r * 32 + lane) * 32 + tgc];
            const float tr = (t == 0) ? __ldg(start_t + tgc)
                                      : __ldg(trans + tgpc * 32 + tgc);
            float co = valid ? (tr + em) : 0.f;
            if (valid && t == len - 1) co += __ldg(end_t + tgc);
            acc += co;
        }
#pragma unroll
        for (int off = 16; off > 0; off >>= 1)
            acc += __shfl_xor_sync(F, acc, off);
        if (lane == 0) g_scorep[b][c] = acc;
    }

    // ======================= tickets + combine ============================
    __syncthreads();
    if (tid == 0) {
        __threadfence();
        const int old = atomicAdd(&g_doneb[b], 1);
        s_win = (old == 3);
        s_win2 = 0;
    }
    __syncthreads();
    if (!s_win) return;

    if (w == 0) {
        // per-batch combine (warp 0): junction terms independent per lane.
        __threadfence();
        const int lenb = g_len[b];
        const int clb = (lenb - 1) >> 4;
        float term = 0.f;
        if (lane >= 1 && lane <= clb) {
            float dotv = 0.f;
            const float* bv = g_bvec[b][lane];
            const float* fv = g_fvec[b][lane - 1];
#pragma unroll
            for (int i = 0; i < 32; i++) dotv += bv[i] * fv[i];
            term = g_blog[b][lane] + __logf(dotv);
            if (lane <= clb - 1) {
                float sumv = 0.f;
                const float* fc = g_fvec[b][lane];
#pragma unroll
                for (int i = 0; i < 32; i++) sumv += fc[i];
                term -= __logf(sumv);
            }
        }
#pragma unroll
        for (int off = 16; off > 0; off >>= 1)
            term += __shfl_xor_sync(F, term, off);
        const float logZ = g_flog[b][0] + term;

        if (lane == 0) {
            float score = 0.f;
#pragma unroll
            for (int cc2 = 0; cc2 < 4; cc2++) score += g_scorep[b][cc2];
            g_llh[b] = score - logZ;
        }
    }
    __syncthreads();
    if (tid == 0) {
        __threadfence();
        const int o2 = atomicAdd(&g_done, 1);
        s_win2 = (o2 == BATCH - 1);
    }
    __syncthreads();
    if (s_win2 && w == 0) {
        __threadfence();
        float v = g_llh[lane] + g_llh[lane + 32];
#pragma unroll
        for (int off = 16; off > 0; off >>= 1)
            v += __shfl_xor_sync(F, v, off);
        if (lane == 0) out[0] = -v * (1.0f / (float)BATCH);
        g_doneb[lane] = 0;
        g_doneb[lane + 32] = 0;
        if (lane == 0) g_done = 0;
    }
}

// ---------------------------------------------------------------------------
extern "C" void kernel_launch(void* const* d_in, const int* in_sizes, int n_in,
                              void* d_out, int out_size) {
    const float* feat    = (const float*)d_in[0];
    const int*   tags    = (const int*)  d_in[1];
    const float* W       = (const float*)d_in[2];
    const float* bias    = (const float*)d_in[3];
    const float* start_t = (const float*)d_in[4];
    const float* end_t   = (const float*)d_in[5];
    const float* trans   = (const float*)d_in[6];
    float* out = (float*)d_out;

    fused_kernel<<<BATCH * 4, 256>>>(feat, tags, W, bias,
                                     start_t, end_t, trans, out);
}